// round 14
// baseline (speedup 1.0000x reference)
#include <cuda_runtime.h>
#include <cstdint>

#define BB 128
#define TT 2048
#define XPS 528   // xp row stride (fits 3H up to 525)

__device__ float g_bufA[(size_t)BB * TT * 180];
__device__ float g_bufB[(size_t)BB * TT * 180];
__device__ float g_xp[(size_t)BB * TT * XPS];
__device__ float g_mask[(size_t)BB * TT];
__device__ float g_h34[BB * 60];
__device__ float g_z[BB * 30];
__device__ float g_Uc[60 * 180];
__device__ float g_Wc[150 * 180];
__device__ float g_bc[2 * 180];

__host__ __device__ constexpr int padDim(int v) {
    int h = (v + 3) / 4 * 4;
    if (((h / 4) & 1) == 0) h += 4;
    return h;
}

__device__ __forceinline__ uint32_t smem_u32(const void* p) {
    uint32_t a;
    asm("{ .reg .u64 t; cvta.to.shared.u64 t, %1; cvt.u32.u64 %0, t; }" : "=r"(a) : "l"(p));
    return a;
}
__device__ __forceinline__ uint32_t mapa_shared(uint32_t local, uint32_t rank) {
    uint32_t r;
    asm("mapa.shared::cluster.u32 %0, %1, %2;" : "=r"(r) : "r"(local), "r"(rank));
    return r;
}
__device__ __forceinline__ void st_cluster_f32(uint32_t addr, float v) {
    asm volatile("st.shared::cluster.b32 [%0], %1;" :: "r"(addr), "r"(__float_as_uint(v)));
}
__device__ __forceinline__ void cluster_sync_() {
    asm volatile("barrier.cluster.arrive.aligned;" ::: "memory");
    asm volatile("barrier.cluster.wait.aligned;" ::: "memory");
}
__device__ __forceinline__ float hsig(float v) { return fminf(fmaxf(0.2f * v + 0.5f, 0.f), 1.f); }
__device__ __forceinline__ float sigm(float v) { return 1.f / (1.f + expf(-v)); }

// ===== persistent GRU, recurrent-only, TWO batch groups per cluster =====
// 16 clusters x 8 CTAs; cluster covers 8 batch rows = 2 groups of BT=4.
// Warps [0, JG) drive group 0, [JG, 2JG) group 1 — both share the smem weight
// tiles and ONE cluster barrier per step (tail amortized over 8 rows).
// Per-group warp = (4 b) x (2 jj); lanes split HP-quads 32 ways; butterfly ->
// in-register epilogue -> DSMEM broadcast to the 8 CTAs (per-group h buffer).
template <int H, int NTH, bool HSIG, bool TANHA, bool UM, bool WSEQ>
__global__ void __cluster_dims__(8, 1, 1) __launch_bounds__(NTH, 1)
gru_kernel(const float* __restrict__ xp, const float* __restrict__ U,
           const float* __restrict__ bias, const float* __restrict__ mask,
           float* __restrict__ out_seq)
{
    constexpr int BT = 4, JJT = 2;
    constexpr int HP = padDim(H);
    constexpr int HQ = HP / 4;
    constexpr int JT = (H + 7) / 8;
    constexpr int JG = (JT + JJT - 1) / JJT;
    constexpr int JTp = JG * JJT;
    constexpr int H3 = 3 * H;
    static_assert(NTH == 64 * JG, "threads = 32 per jj-group per batch-group");

    extern __shared__ float smem[];
    float* sW   = smem;                     // JTp*3*HP (zero-padded), shared by both groups
    float* sv   = sW + JTp * 3 * HP;        // [group][phase][BT][HP] = 4*BT*HP
    float* sbz  = sv + 4 * BT * HP;
    float* sbr  = sbz + JTp;
    float* sbrh = sbr + JTp;
    float* sbxh = sbrh + JTp;
    constexpr int SMTOT = JTp * 3 * HP + 4 * BT * HP + 4 * JTp;

    const int tid  = threadIdx.x;
    const int rank = blockIdx.x & 7;
    const int ci   = blockIdx.x >> 3;
    const int j0   = rank * JT;

    for (int e = tid; e < SMTOT; e += NTH) smem[e] = 0.f;
    __syncthreads();

    // recurrent weights only: row (jj,g) = U[:,g*H+j], zero-padded to HP
    for (int e = tid; e < JT * 3 * HP; e += NTH) {
        int jj = e / (3 * HP);
        int r  = e - jj * (3 * HP);
        int g  = r / HP;
        int k  = r - g * HP;
        int j  = j0 + jj;
        float val = 0.f;
        if (j < H && k < H) val = U[k * H3 + g * H + j];
        sW[(jj * 3 + g) * HP + k] = val;
    }
    if (tid < JT) {
        int j = j0 + tid;
        if (j < H) {
            sbz[tid]  = bias[j] + bias[H3 + j];
            sbr[tid]  = bias[H + j] + bias[H3 + H + j];
            sbxh[tid] = bias[2 * H + j];
            sbrh[tid] = bias[H3 + 2 * H + j];
        }
    }
    __syncthreads();

    const uint32_t svu = smem_u32(sv);
    uint32_t rb[8];
#pragma unroll
    for (int r = 0; r < 8; r++) rb[r] = mapa_shared(svu, (uint32_t)r);
    cluster_sync_();   // all CTAs' h buffers zeroed before any remote store

    const int w = tid >> 5, lane = tid & 31;
    const int wg = (w >= JG) ? 1 : 0;       // batch group of this warp
    const int wl = w - wg * JG;             // warp index within group
    const int b0 = ci * 8 + wg * BT;        // first batch row of this group
    // owner decode: item = bit-reversal of lane bits 0..2; item = b*2 + jl
    const int oitem = ((lane & 1) << 2) | (lane & 2) | ((lane & 4) >> 2);
    const int ob = oitem >> 1, ojl = oitem & 1;
    const int ojj = wl * JJT + ojl;
    const int oj  = j0 + ojj;
    const bool oval = (lane < 8) && (ojj < JT) && (oj < H);
    const float* xrow0 = xp + (size_t)(b0 + ob) * TT * XPS + oj;

    int p = 0;
    for (int t = 0; t < TT; t++) {
        const int nxt = 1 - p;

        // early xp(t) + mask(t) loads (latency hidden by FMA phase below)
        float xz = 0.f, xr = 0.f, xh = 0.f, mkv = 1.f;
        if (oval) {
            const float* xrow = xrow0 + (size_t)t * XPS;
            xz = __ldg(xrow);
            xr = __ldg(xrow + H);
            xh = __ldg(xrow + 2 * H);
            if (UM) mkv = __ldg(mask + (size_t)(b0 + ob) * TT + t);
        }

        // ---- recurrent accumulation over this group's h buffer
        const float* vc = sv + (wg * 2 + p) * BT * HP;
        float accf[24];
#pragma unroll
        for (int a = 0; a < 24; a++) accf[a] = 0.f;

        for (int g4 = lane; g4 < HQ; g4 += 32) {
            const float* vq = vc + g4 * 4;
            float4 vb[BT];
#pragma unroll
            for (int b = 0; b < BT; ++b)
                vb[b] = *reinterpret_cast<const float4*>(vq + b * HP);
#pragma unroll
            for (int jl = 0; jl < JJT; ++jl) {
                const float* wb = sW + ((wl * JJT + jl) * 3) * HP + g4 * 4;
                float4 wz = *reinterpret_cast<const float4*>(wb);
                float4 wr = *reinterpret_cast<const float4*>(wb + HP);
                float4 wh = *reinterpret_cast<const float4*>(wb + 2 * HP);
#pragma unroll
                for (int b = 0; b < BT; ++b) {
                    const int a = (b * JJT + jl) * 3;
                    accf[a+0] = fmaf(vb[b].x, wz.x, accf[a+0]);
                    accf[a+0] = fmaf(vb[b].y, wz.y, accf[a+0]);
                    accf[a+0] = fmaf(vb[b].z, wz.z, accf[a+0]);
                    accf[a+0] = fmaf(vb[b].w, wz.w, accf[a+0]);
                    accf[a+1] = fmaf(vb[b].x, wr.x, accf[a+1]);
                    accf[a+1] = fmaf(vb[b].y, wr.y, accf[a+1]);
                    accf[a+1] = fmaf(vb[b].z, wr.z, accf[a+1]);
                    accf[a+1] = fmaf(vb[b].w, wr.w, accf[a+1]);
                    accf[a+2] = fmaf(vb[b].x, wh.x, accf[a+2]);
                    accf[a+2] = fmaf(vb[b].y, wh.y, accf[a+2]);
                    accf[a+2] = fmaf(vb[b].z, wh.z, accf[a+2]);
                    accf[a+2] = fmaf(vb[b].w, wh.w, accf[a+2]);
                }
            }
        }

        // ---- splitting butterfly: 24 accs (8 items x 3 gates) over lane bits 0..2
#pragma unroll
        for (int s = 0; s < 3; ++s) {
            const int n = 24 >> (s + 1);   // 12, 6, 3
            const bool hi = (lane >> s) & 1;
#pragma unroll
            for (int i = 0; i < n; ++i) {
                float send = hi ? accf[i] : accf[i + n];
                float recv = __shfl_xor_sync(0xffffffffu, send, 1 << s);
                accf[i] = (hi ? accf[i + n] : accf[i]) + recv;
            }
        }
        // broadcast-add across lane bits 3 and 4, keeping 3 gate accs
#pragma unroll
        for (int m = 8; m <= 16; m <<= 1)
#pragma unroll
            for (int i = 0; i < 3; ++i)
                accf[i] += __shfl_xor_sync(0xffffffffu, accf[i], m);

        // ---- in-register epilogue on owner lanes
        if (oval) {
            float az  = accf[0] + xz + sbz[ojj];
            float ar  = accf[1] + xr + sbr[ojj];
            float arh = accf[2] + sbrh[ojj];
            float axh = xh + sbxh[ojj];
            float z = HSIG ? hsig(az) : sigm(az);
            float r = HSIG ? hsig(ar) : sigm(ar);
            float hh = axh + r * arh;
            if (TANHA) hh = tanhf(hh);
            float hprev = vc[ob * HP + oj];
            float hn = z * hprev + (1.f - z) * hh;
            if (UM) { if (mkv == 0.f) hn = hprev; }

            const uint32_t off = (uint32_t)((((wg * 2 + nxt) * BT + ob) * HP + oj) * 4);
#pragma unroll
            for (int r8 = 0; r8 < 8; r8++) st_cluster_f32(rb[r8] + off, hn);

            if (WSEQ) out_seq[((size_t)(b0 + ob) * TT + t) * HP + oj] = hn;
        }
        cluster_sync_();   // one barrier serves BOTH groups
        p = nxt;
    }

    if (!WSEQ) {
        if (tid < 2 * JT * BT) {
            const int wg2 = tid / (JT * BT);
            const int r   = tid - wg2 * (JT * BT);
            const int b = r & 3, jj = r >> 2;
            const int j = j0 + jj;
            if (j < H)
                out_seq[(size_t)(ci * 8 + wg2 * BT + b) * H + j] =
                    sv[((wg2 * 2 + p) * BT + b) * HP + j];
        }
    }
}

// ===== SGEMM: C[M, N] = A[M, K] * W[K, N];  A row-stride lda, C row-stride XPS =====
__global__ void __launch_bounds__(256)
sgemm_kernel(const float* __restrict__ A, int lda, int K,
             const float* __restrict__ W, int N, float* __restrict__ C)
{
    __shared__ float As[16][132];
    __shared__ float Ws[16][64];
    const int tid = threadIdx.x;
    const int m0 = blockIdx.x * 128;
    const int n0 = blockIdx.y * 64;
    const int tr = tid >> 4;
    const int tc = tid & 15;

    float acc[8][4];
#pragma unroll
    for (int r = 0; r < 8; r++)
#pragma unroll
        for (int c = 0; c < 4; c++) acc[r][c] = 0.f;

    for (int k0 = 0; k0 < K; k0 += 16) {
        for (int i = tid; i < 128 * 16; i += 256) {
            int row = i >> 4, kk = i & 15;
            int gk = k0 + kk;
            As[kk][row] = (gk < K) ? A[(size_t)(m0 + row) * lda + gk] : 0.f;
        }
        for (int i = tid; i < 16 * 64; i += 256) {
            int kk = i >> 6, nn = i & 63;
            int gk = k0 + kk, gn = n0 + nn;
            Ws[kk][nn] = (gk < K && gn < N) ? W[(size_t)gk * N + gn] : 0.f;
        }
        __syncthreads();
#pragma unroll
        for (int kk = 0; kk < 16; kk++) {
            float4 a0 = *reinterpret_cast<const float4*>(&As[kk][tr * 8]);
            float4 a1 = *reinterpret_cast<const float4*>(&As[kk][tr * 8 + 4]);
            float4 bv = *reinterpret_cast<const float4*>(&Ws[kk][tc * 4]);
            float av[8] = {a0.x, a0.y, a0.z, a0.w, a1.x, a1.y, a1.z, a1.w};
            float bb[4] = {bv.x, bv.y, bv.z, bv.w};
#pragma unroll
            for (int r = 0; r < 8; r++)
#pragma unroll
                for (int c = 0; c < 4; c++)
                    acc[r][c] = fmaf(av[r], bb[c], acc[r][c]);
        }
        __syncthreads();
    }
    const int nbase = n0 + tc * 4;
#pragma unroll
    for (int r = 0; r < 8; r++) {
        float* crow = C + (size_t)(m0 + tr * 8 + r) * XPS + nbase;
#pragma unroll
        for (int c = 0; c < 4; c++)
            if (nbase + c < N) crow[c] = acc[r][c];
    }
}

// ===================== small kernels =====================
__global__ void mask_kernel(const float* __restrict__ x, float* __restrict__ m) {
    int idx = blockIdx.x * blockDim.x + threadIdx.x;
    if (idx < BB * TT) {
        float4 v = ((const float4*)x)[idx];
        m[idx] = (v.x != 0.f || v.y != 0.f || v.z != 0.f || v.w != 0.f) ? 1.f : 0.f;
    }
}

__global__ void combine34_kernel(const float* __restrict__ W3, const float* __restrict__ U3,
                                 const float* __restrict__ b3, const float* __restrict__ W4,
                                 const float* __restrict__ U4, const float* __restrict__ b4,
                                 float* __restrict__ Uc, float* __restrict__ Wc,
                                 float* __restrict__ bc) {
    const int NU = 60 * 180, NW = 150 * 180, NBc = 2 * 180;
    for (int e = blockIdx.x * blockDim.x + threadIdx.x; e < NU + NW + NBc;
         e += gridDim.x * blockDim.x) {
        if (e < NU) {
            int k = e / 180, col = e % 180;
            int g = col / 60, jj = col % 60;
            float v = 0.f;
            if (jj < 30) { if (k < 30)  v = U3[k * 90 + g * 30 + jj]; }
            else         { if (k >= 30) v = U4[(k - 30) * 90 + g * 30 + (jj - 30)]; }
            Uc[e] = v;
        } else if (e < NU + NW) {
            int e2 = e - NU;
            int i = e2 / 180, col = e2 % 180;
            int g = col / 60, jj = col % 60;
            Wc[e2] = (jj < 30) ? W3[i * 90 + g * 30 + jj] : W4[i * 90 + g * 30 + (jj - 30)];
        } else {
            int e2 = e - NU - NW;
            int rr = e2 / 180, col = e2 % 180;
            int g = col / 60, jj = col % 60;
            bc[e2] = (jj < 30) ? b3[rr * 90 + g * 30 + jj] : b4[rr * 90 + g * 30 + (jj - 30)];
        }
    }
}

__global__ void z_kernel(const float* __restrict__ h34, const float* __restrict__ eps,
                         float* __restrict__ z) {
    int idx = blockIdx.x * blockDim.x + threadIdx.x;
    if (idx < BB * 30) {
        int b = idx / 30, c = idx % 30;
        z[idx] = h34[b * 60 + c] + expf(0.5f * h34[b * 60 + 30 + c]) * eps[idx];
    }
}

__global__ void decin_kernel(const float* __restrict__ z, const float* __restrict__ tin2,
                             const float* __restrict__ masks, float* __restrict__ dec_in) {
    const size_t N = (size_t)BB * TT * 36;
    for (size_t idx = (size_t)blockIdx.x * blockDim.x + threadIdx.x; idx < N;
         idx += (size_t)gridDim.x * blockDim.x) {
        size_t b = idx / ((size_t)TT * 36);
        size_t rem = idx % ((size_t)TT * 36);
        size_t t = rem / 36;
        int c = (int)(rem % 36);
        float v = 0.f;
        if (c < 30)      v = z[b * 30 + c] * masks[(b * TT + t) * 32 + c];
        else if (c < 32) v = tin2[(b * TT + t) * 2 + (c - 30)] * masks[(b * TT + t) * 32 + c];
        dec_in[idx] = v;
    }
}

__global__ void dense_kernel(const float* __restrict__ h6, const float* __restrict__ Wd,
                             const float* __restrict__ bd, const float* __restrict__ dec_masks,
                             float* __restrict__ out) {
    int gtid = blockIdx.x * blockDim.x + threadIdx.x;
    int row = gtid >> 5;
    int lane = gtid & 31;
    if (row >= BB * TT) return;
    float s = 0.f;
    const float* hrow = h6 + (size_t)row * 180;
    for (int k = lane; k < 175; k += 32) s = fmaf(hrow[k], Wd[k], s);
#pragma unroll
    for (int off = 16; off; off >>= 1) s += __shfl_down_sync(0xffffffffu, s, off);
    if (lane == 0) out[row] = tanhf(s + bd[0]) * dec_masks[row];
}

// ===================== host-side launch helpers =====================
template <int H, int NTH, bool HSIG, bool TANHA, bool UM, bool WSEQ>
static void launch_gru(const float* xp, const float* U, const float* bias,
                       const float* mask, float* out_seq) {
    constexpr int BT = 4, JJT = 2;
    constexpr int HP = padDim(H);
    constexpr int JT = (H + 7) / 8;
    constexpr int JG = (JT + JJT - 1) / JJT;
    constexpr int JTp = JG * JJT;
    constexpr int SMTOT = JTp * 3 * HP + 4 * BT * HP + 4 * JTp;
    constexpr int smem_bytes = SMTOT * 4;
    auto fn = gru_kernel<H, NTH, HSIG, TANHA, UM, WSEQ>;
    cudaFuncSetAttribute(fn, cudaFuncAttributeMaxDynamicSharedMemorySize, smem_bytes);
    cudaFuncSetAttribute(fn, cudaFuncAttributeNonPortableClusterSizeAllowed, 1);
    fn<<<128, NTH, smem_bytes>>>(xp, U, bias, mask, out_seq);
}

static void launch_sgemm(const float* A, int lda, int K, const float* W, int N, float* C) {
    dim3 grid(BB * TT / 128, (N + 63) / 64);
    sgemm_kernel<<<grid, 256>>>(A, lda, K, W, N, C);
}

extern "C" void kernel_launch(void* const* d_in, const int* in_sizes, int n_in,
                              void* d_out, int out_size) {
    const float* x         = (const float*)d_in[0];
    const float* tin2      = (const float*)d_in[1];
    const float* masks     = (const float*)d_in[2];
    const float* dec_masks = (const float*)d_in[3];
    const float* eps       = (const float*)d_in[4];
    const float* W1 = (const float*)d_in[5];
    const float* U1 = (const float*)d_in[6];
    const float* b1 = (const float*)d_in[7];
    const float* W2 = (const float*)d_in[8];
    const float* U2 = (const float*)d_in[9];
    const float* b2 = (const float*)d_in[10];
    const float* W3 = (const float*)d_in[11];
    const float* U3 = (const float*)d_in[12];
    const float* b3 = (const float*)d_in[13];
    const float* W4 = (const float*)d_in[14];
    const float* U4 = (const float*)d_in[15];
    const float* b4 = (const float*)d_in[16];
    const float* W5 = (const float*)d_in[17];
    const float* U5 = (const float*)d_in[18];
    const float* b5 = (const float*)d_in[19];
    const float* W6 = (const float*)d_in[20];
    const float* U6 = (const float*)d_in[21];
    const float* b6 = (const float*)d_in[22];
    const float* Wd = (const float*)d_in[23];
    const float* bd = (const float*)d_in[24];
    float* out = (float*)d_out;

    void *pA, *pB, *pX, *pM, *pH34, *pZ, *pUc, *pWc, *pBc;
    cudaGetSymbolAddress(&pA, g_bufA);
    cudaGetSymbolAddress(&pB, g_bufB);
    cudaGetSymbolAddress(&pX, g_xp);
    cudaGetSymbolAddress(&pM, g_mask);
    cudaGetSymbolAddress(&pH34, g_h34);
    cudaGetSymbolAddress(&pZ, g_z);
    cudaGetSymbolAddress(&pUc, g_Uc);
    cudaGetSymbolAddress(&pWc, g_Wc);
    cudaGetSymbolAddress(&pBc, g_bc);
    float* bufA = (float*)pA;
    float* bufB = (float*)pB;
    float* xpb  = (float*)pX;
    float* mptr = (float*)pM;
    float* h34  = (float*)pH34;
    float* zbuf = (float*)pZ;
    float* Uc   = (float*)pUc;
    float* Wc   = (float*)pWc;
    float* Bc   = (float*)pBc;

    mask_kernel<<<(BB * TT + 255) / 256, 256>>>(x, mptr);
    combine34_kernel<<<64, 256>>>(W3, U3, b3, W4, U4, b4, Uc, Wc, Bc);

    // encoder GRU1 (H=175, I=4): JG=11 -> 704 threads
    launch_sgemm(x, 4, 4, W1, 525, xpb);
    launch_gru<175, 704, true, true, true, true>(xpb, U1, b1, mptr, bufA);

    // encoder GRU2 (H=150, I=175): JG=10 -> 640 threads
    launch_sgemm(bufA, 180, 175, W2, 450, xpb);
    launch_gru<150, 640, true, true, true, true>(xpb, U2, b2, mptr, bufB);

    // fused GRU3+GRU4 (H=60, I=150): JG=4 -> 256 threads, final state only
    launch_sgemm(bufB, 156, 150, Wc, 180, xpb);
    launch_gru<60, 256, false, false, true, false>(xpb, Uc, Bc, mptr, h34);

    // reparameterize + decoder input (stride 36)
    z_kernel<<<(BB * 30 + 255) / 256, 256>>>(h34, eps, zbuf);
    decin_kernel<<<2048, 256>>>(zbuf, tin2, masks, bufA);

    // decoder GRU5 (H=150, I=32): 640 threads
    launch_sgemm(bufA, 36, 32, W5, 450, xpb);
    launch_gru<150, 640, true, true, false, true>(xpb, U5, b5, nullptr, bufB);

    // decoder GRU6 (H=175, I=150): 704 threads
    launch_sgemm(bufB, 156, 150, W6, 525, xpb);
    launch_gru<175, 704, true, true, false, true>(xpb, U6, b6, nullptr, bufA);

    dense_kernel<<<(BB * TT + 7) / 8, 256>>>(bufA, Wd, bd, dec_masks, out);
}

// round 15
// speedup vs baseline: 1.9239x; 1.9239x over previous
#include <cuda_runtime.h>
#include <cstdint>

#define BB 128
#define TT 2048

__device__ float g_bufA[(size_t)BB * TT * 180];
__device__ float g_bufB[(size_t)BB * TT * 180];
__device__ float g_mask[(size_t)BB * TT];
__device__ float g_h34[BB * 60];
__device__ float g_z[BB * 30];
__device__ float g_Uc[60 * 180];
__device__ float g_Wc[150 * 180];
__device__ float g_bc[2 * 180];

__host__ __device__ constexpr int padDim(int v) {
    int h = (v + 3) / 4 * 4;
    if (((h / 4) & 1) == 0) h += 4;
    return h;
}

__device__ __forceinline__ uint32_t smem_u32(const void* p) {
    uint32_t a;
    asm("{ .reg .u64 t; cvta.to.shared.u64 t, %1; cvt.u32.u64 %0, t; }" : "=r"(a) : "l"(p));
    return a;
}
__device__ __forceinline__ uint32_t mapa_shared(uint32_t local, uint32_t rank) {
    uint32_t r;
    asm("mapa.shared::cluster.u32 %0, %1, %2;" : "=r"(r) : "r"(local), "r"(rank));
    return r;
}
__device__ __forceinline__ void st_cluster_f32(uint32_t addr, float v) {
    asm volatile("st.shared::cluster.b32 [%0], %1;" :: "r"(addr), "r"(__float_as_uint(v)));
}
__device__ __forceinline__ void cluster_sync_() {
    asm volatile("barrier.cluster.arrive.aligned;" ::: "memory");
    asm volatile("barrier.cluster.wait.aligned;" ::: "memory");
}
__device__ __forceinline__ void cp_async16(uint32_t dst, const void* src) {
    asm volatile("cp.async.cg.shared.global [%0], [%1], 16;" :: "r"(dst), "l"(src));
}
__device__ __forceinline__ void cp_async4(uint32_t dst, const void* src) {
    asm volatile("cp.async.ca.shared.global [%0], [%1], 4;" :: "r"(dst), "l"(src));
}
__device__ __forceinline__ void cp_commit() {
    asm volatile("cp.async.commit_group;" ::: "memory");
}
__device__ __forceinline__ void cp_wait0() {
    asm volatile("cp.async.wait_group 0;" ::: "memory");
}

__device__ __forceinline__ float hsig(float v) { return fminf(fmaxf(0.2f * v + 0.5f, 0.f), 1.f); }
__device__ __forceinline__ float sigm(float v) { return 1.f / (1.f + expf(-v)); }

// ===================== persistent GRU kernel (register-tiled, 2 CTA/SM) =====================
// 32 clusters of 8 CTAs; cluster handles BT=4 batch rows; CTA rank owns hidden
// tile [j0, j0+JT). One warp owns (4 b) x (4 jj); lanes split K-quads 32 ways.
// Butterfly reduction leaves all 4 gate accumulators DUPLICATED in lane l and
// l^16 -> BOTH half-warps run the epilogue; each issues only 4 of the 8 DSMEM
// broadcast stores (halves the serial store chain on the step critical path).
// One cluster barrier per step. 2 CTAs/SM so sync latency of one cluster
// overlaps compute of the other.
template <int H, int I, int NTH, bool HSIG, bool TANHA, bool UM, bool WSEQ>
__global__ void __cluster_dims__(8, 1, 1) __launch_bounds__(NTH, 2)
gru_kernel(const float* __restrict__ in_seq, const float* __restrict__ U,
           const float* __restrict__ W, const float* __restrict__ bias,
           const float* __restrict__ mask, float* __restrict__ out_seq)
{
    constexpr int BT = 4, JJT = 4;
    constexpr int HP = padDim(H), IP = padDim(I), KP = HP + IP;
    constexpr int Q = KP / 4, HQ = HP / 4;
    constexpr int JT = (H + 7) / 8;
    constexpr int JG = (JT + JJT - 1) / JJT;
    constexpr int JTp = JG * JJT;
    constexpr int H3 = 3 * H;
    static_assert(NTH == 32 * JG, "threads = 32 per jj-group");

    extern __shared__ float smem[];
    float* sW   = smem;                     // JTp*3*KP (rows zero-padded)
    float* sv   = sW + JTp * 3 * KP;        // 2*BT*KP  (double-buffered [h|x])
    float* sbz  = sv + 2 * BT * KP;         // JTp
    float* sbr  = sbz + JTp;
    float* sbrh = sbr + JTp;
    float* sbxh = sbrh + JTp;
    float* smk  = sbxh + JTp;               // 2*BT
    constexpr int SMTOT = JTp * 3 * KP + 2 * BT * KP + 4 * JTp + 2 * BT;

    const int tid  = threadIdx.x;
    const int rank = blockIdx.x & 7;
    const int ci   = blockIdx.x >> 3;
    const int b0   = ci * BT;
    const int j0   = rank * JT;

    for (int e = tid; e < SMTOT; e += NTH) smem[e] = 0.f;
    __syncthreads();

    // weights: row (jj,g) = [U[:,g*H+j] (k<HP) | W[:,g*H+j] (k>=HP)], zero-padded
    for (int e = tid; e < JT * 3 * KP; e += NTH) {
        int jj = e / (3 * KP);
        int r  = e - jj * (3 * KP);
        int g  = r / KP;
        int k  = r - g * KP;
        int j  = j0 + jj;
        float val = 0.f;
        if (j < H) {
            if (k < HP) { if (k < H) val = U[k * H3 + g * H + j]; }
            else { int i = k - HP; if (i < I) val = W[i * H3 + g * H + j]; }
        }
        sW[(jj * 3 + g) * KP + k] = val;
    }
    if (tid < JT) {
        int j = j0 + tid;
        if (j < H) {
            sbz[tid]  = bias[j] + bias[H3 + j];
            sbr[tid]  = bias[H + j] + bias[H3 + H + j];
            sbxh[tid] = bias[2 * H + j];
            sbrh[tid] = bias[H3 + 2 * H + j];
        }
    }
    __syncthreads();

    const uint32_t svu = smem_u32(sv);
    uint32_t rb[8];
#pragma unroll
    for (int r = 0; r < 8; r++) rb[r] = mapa_shared(svu, (uint32_t)r);

    // stage x(0), mask(0) into phase 0
    constexpr int XOPS = BT * (IP / 4);
    for (int e = tid; e < XOPS; e += NTH) {
        int bb = e / (IP / 4), i4 = e - bb * (IP / 4);
        cp_async16(svu + (uint32_t)((bb * KP + HP + i4 * 4) * 4),
                   in_seq + ((size_t)(b0 + bb) * TT) * IP + i4 * 4);
    }
    if (UM && tid < BT)
        cp_async4(smem_u32(smk + tid), mask + (size_t)(b0 + tid) * TT);
    cp_commit();
    cp_wait0();
    cluster_sync_();

    const int w = tid >> 5, lane = tid & 31;
    // owner decode uses lane bits 0..3 only -> identical for lane and lane^16
    const int item = ((lane & 1) << 3) | ((lane & 2) << 1) |
                     ((lane & 4) >> 1) | ((lane & 8) >> 3);
    const int ob = item >> 2, ojl = item & 3;
    const int ojj = w * JJT + ojl;
    const int oj  = j0 + ojj;
    const bool oval = (ojj < JT) && (oj < H);
    const int rbase0 = (lane < 16) ? 0 : 4;   // store-range split across half-warps

    int p = 0;
    for (int t = 0; t < TT; t++) {
        const int nxt = 1 - p;
        // prefetch x(t+1), mask(t+1)
        if (t + 1 < TT) {
            for (int e = tid; e < XOPS; e += NTH) {
                int bb = e / (IP / 4), i4 = e - bb * (IP / 4);
                cp_async16(svu + (uint32_t)(((nxt * BT + bb) * KP + HP + i4 * 4) * 4),
                           in_seq + ((size_t)(b0 + bb) * TT + (t + 1)) * IP + i4 * 4);
            }
            if (UM && tid < BT)
                cp_async4(smem_u32(smk + nxt * BT + tid),
                          mask + (size_t)(b0 + tid) * TT + (t + 1));
        }
        cp_commit();

        // ---- main accumulation: warp covers 4 b x 4 jj, lanes stride quads
        const float* vc = sv + p * BT * KP;
        float accf[64];
#pragma unroll
        for (int a = 0; a < 64; a++) accf[a] = 0.f;

        for (int g4 = lane; g4 < Q; g4 += 32) {
            const float* vq = vc + g4 * 4;
            float4 vb[BT];
#pragma unroll
            for (int b = 0; b < BT; ++b)
                vb[b] = *reinterpret_cast<const float4*>(vq + b * KP);
            float4 whv[JJT];
#pragma unroll
            for (int jl = 0; jl < JJT; ++jl) {
                const float* wb = sW + ((w * JJT + jl) * 3) * KP + g4 * 4;
                float4 wz = *reinterpret_cast<const float4*>(wb);
                float4 wr = *reinterpret_cast<const float4*>(wb + KP);
                whv[jl]   = *reinterpret_cast<const float4*>(wb + 2 * KP);
#pragma unroll
                for (int b = 0; b < BT; ++b) {
                    const int a = (b * JJT + jl) * 4;
                    accf[a+0] = fmaf(vb[b].x, wz.x, accf[a+0]);
                    accf[a+0] = fmaf(vb[b].y, wz.y, accf[a+0]);
                    accf[a+0] = fmaf(vb[b].z, wz.z, accf[a+0]);
                    accf[a+0] = fmaf(vb[b].w, wz.w, accf[a+0]);
                    accf[a+1] = fmaf(vb[b].x, wr.x, accf[a+1]);
                    accf[a+1] = fmaf(vb[b].y, wr.y, accf[a+1]);
                    accf[a+1] = fmaf(vb[b].z, wr.z, accf[a+1]);
                    accf[a+1] = fmaf(vb[b].w, wr.w, accf[a+1]);
                }
            }
            if (g4 < HQ) {   // h-range: gate-h -> recurrent accumulator (a+2)
#pragma unroll
                for (int jl = 0; jl < JJT; ++jl)
#pragma unroll
                    for (int b = 0; b < BT; ++b) {
                        const int a = (b * JJT + jl) * 4;
                        accf[a+2] = fmaf(vb[b].x, whv[jl].x, accf[a+2]);
                        accf[a+2] = fmaf(vb[b].y, whv[jl].y, accf[a+2]);
                        accf[a+2] = fmaf(vb[b].z, whv[jl].z, accf[a+2]);
                        accf[a+2] = fmaf(vb[b].w, whv[jl].w, accf[a+2]);
                    }
            } else {         // x-range: gate-h -> input accumulator (a+3)
#pragma unroll
                for (int jl = 0; jl < JJT; ++jl)
#pragma unroll
                    for (int b = 0; b < BT; ++b) {
                        const int a = (b * JJT + jl) * 4;
                        accf[a+3] = fmaf(vb[b].x, whv[jl].x, accf[a+3]);
                        accf[a+3] = fmaf(vb[b].y, whv[jl].y, accf[a+3]);
                        accf[a+3] = fmaf(vb[b].z, whv[jl].z, accf[a+3]);
                        accf[a+3] = fmaf(vb[b].w, whv[jl].w, accf[a+3]);
                    }
            }
        }

        // ---- splitting butterfly: 4 rounds over lane bits 0..3
#pragma unroll
        for (int s = 0; s < 4; ++s) {
            const int n = 64 >> (s + 1);
            const bool hi = (lane >> s) & 1;
#pragma unroll
            for (int i = 0; i < n; ++i) {
                float send = hi ? accf[i] : accf[i + n];
                float recv = __shfl_xor_sync(0xffffffffu, send, 1 << s);
                accf[i] = (hi ? accf[i + n] : accf[i]) + recv;
            }
        }
        // finish across lane bit 4 -> full sums DUPLICATED in lanes l and l^16
#pragma unroll
        for (int i = 0; i < 4; ++i)
            accf[i] += __shfl_xor_sync(0xffffffffu, accf[i], 16);

        // ---- in-register epilogue on BOTH half-warps (identical values);
        //      each half issues 4 of the 8 DSMEM broadcast stores
        if (oval) {
            float az  = accf[0] + sbz[ojj];
            float ar  = accf[1] + sbr[ojj];
            float arh = accf[2] + sbrh[ojj];
            float axh = accf[3] + sbxh[ojj];
            float z = HSIG ? hsig(az) : sigm(az);
            float r = HSIG ? hsig(ar) : sigm(ar);
            float hh = axh + r * arh;
            if (TANHA) hh = tanhf(hh);
            float hprev = vc[ob * KP + oj];
            float hn = z * hprev + (1.f - z) * hh;
            if (UM) { if (smk[p * BT + ob] == 0.f) hn = hprev; }

            const uint32_t off = (uint32_t)(((nxt * BT + ob) * KP + oj) * 4);
#pragma unroll
            for (int r4 = 0; r4 < 4; r4++) st_cluster_f32(rb[rbase0 + r4] + off, hn);

            if (WSEQ && lane < 16) out_seq[((size_t)(b0 + ob) * TT + t) * HP + oj] = hn;
        }
        cp_wait0();
        cluster_sync_();
        p = nxt;
    }

    if (!WSEQ) {
        if (tid < JT * BT) {
            const int b = tid & 3, jj = tid >> 2;
            const int j = j0 + jj;
            if (j < H) out_seq[(size_t)(b0 + b) * H + j] = sv[(p * BT + b) * KP + j];
        }
    }
}

// ===================== small kernels =====================
__global__ void mask_kernel(const float* __restrict__ x, float* __restrict__ m) {
    int idx = blockIdx.x * blockDim.x + threadIdx.x;
    if (idx < BB * TT) {
        float4 v = ((const float4*)x)[idx];
        m[idx] = (v.x != 0.f || v.y != 0.f || v.z != 0.f || v.w != 0.f) ? 1.f : 0.f;
    }
}

__global__ void combine34_kernel(const float* __restrict__ W3, const float* __restrict__ U3,
                                 const float* __restrict__ b3, const float* __restrict__ W4,
                                 const float* __restrict__ U4, const float* __restrict__ b4,
                                 float* __restrict__ Uc, float* __restrict__ Wc,
                                 float* __restrict__ bc) {
    const int NU = 60 * 180, NW = 150 * 180, NBc = 2 * 180;
    for (int e = blockIdx.x * blockDim.x + threadIdx.x; e < NU + NW + NBc;
         e += gridDim.x * blockDim.x) {
        if (e < NU) {
            int k = e / 180, col = e % 180;
            int g = col / 60, jj = col % 60;
            float v = 0.f;
            if (jj < 30) { if (k < 30)  v = U3[k * 90 + g * 30 + jj]; }
            else         { if (k >= 30) v = U4[(k - 30) * 90 + g * 30 + (jj - 30)]; }
            Uc[e] = v;
        } else if (e < NU + NW) {
            int e2 = e - NU;
            int i = e2 / 180, col = e2 % 180;
            int g = col / 60, jj = col % 60;
            Wc[e2] = (jj < 30) ? W3[i * 90 + g * 30 + jj] : W4[i * 90 + g * 30 + (jj - 30)];
        } else {
            int e2 = e - NU - NW;
            int rr = e2 / 180, col = e2 % 180;
            int g = col / 60, jj = col % 60;
            bc[e2] = (jj < 30) ? b3[rr * 90 + g * 30 + jj] : b4[rr * 90 + g * 30 + (jj - 30)];
        }
    }
}

__global__ void z_kernel(const float* __restrict__ h34, const float* __restrict__ eps,
                         float* __restrict__ z) {
    int idx = blockIdx.x * blockDim.x + threadIdx.x;
    if (idx < BB * 30) {
        int b = idx / 30, c = idx % 30;
        z[idx] = h34[b * 60 + c] + expf(0.5f * h34[b * 60 + 30 + c]) * eps[idx];
    }
}

__global__ void decin_kernel(const float* __restrict__ z, const float* __restrict__ tin2,
                             const float* __restrict__ masks, float* __restrict__ dec_in) {
    const size_t N = (size_t)BB * TT * 36;
    for (size_t idx = (size_t)blockIdx.x * blockDim.x + threadIdx.x; idx < N;
         idx += (size_t)gridDim.x * blockDim.x) {
        size_t b = idx / ((size_t)TT * 36);
        size_t rem = idx % ((size_t)TT * 36);
        size_t t = rem / 36;
        int c = (int)(rem % 36);
        float v = 0.f;
        if (c < 30)      v = z[b * 30 + c] * masks[(b * TT + t) * 32 + c];
        else if (c < 32) v = tin2[(b * TT + t) * 2 + (c - 30)] * masks[(b * TT + t) * 32 + c];
        dec_in[idx] = v;
    }
}

__global__ void dense_kernel(const float* __restrict__ h6, const float* __restrict__ Wd,
                             const float* __restrict__ bd, const float* __restrict__ dec_masks,
                             float* __restrict__ out) {
    int gtid = blockIdx.x * blockDim.x + threadIdx.x;
    int row = gtid >> 5;
    int lane = gtid & 31;
    if (row >= BB * TT) return;
    float s = 0.f;
    const float* hrow = h6 + (size_t)row * 180;
    for (int k = lane; k < 175; k += 32) s = fmaf(hrow[k], Wd[k], s);
#pragma unroll
    for (int off = 16; off; off >>= 1) s += __shfl_down_sync(0xffffffffu, s, off);
    if (lane == 0) out[row] = tanhf(s + bd[0]) * dec_masks[row];
}

// ===================== host-side launch helper =====================
template <int H, int I, int NTH, bool HSIG, bool TANHA, bool UM, bool WSEQ>
static void launch_gru(const float* in_seq, const float* U, const float* W, const float* bias,
                       const float* mask, float* out_seq) {
    constexpr int BT = 4, JJT = 4;
    constexpr int HP = padDim(H), IP = padDim(I), KP = HP + IP;
    constexpr int JT = (H + 7) / 8;
    constexpr int JG = (JT + JJT - 1) / JJT;
    constexpr int JTp = JG * JJT;
    constexpr int SMTOT = JTp * 3 * KP + 2 * BT * KP + 4 * JTp + 2 * BT;
    constexpr int smem_bytes = SMTOT * 4;
    auto fn = gru_kernel<H, I, NTH, HSIG, TANHA, UM, WSEQ>;
    cudaFuncSetAttribute(fn, cudaFuncAttributeMaxDynamicSharedMemorySize, smem_bytes);
    cudaFuncSetAttribute(fn, cudaFuncAttributeNonPortableClusterSizeAllowed, 1);
    fn<<<256, NTH, smem_bytes>>>(in_seq, U, W, bias, mask, out_seq);
}

extern "C" void kernel_launch(void* const* d_in, const int* in_sizes, int n_in,
                              void* d_out, int out_size) {
    const float* x         = (const float*)d_in[0];
    const float* tin2      = (const float*)d_in[1];
    const float* masks     = (const float*)d_in[2];
    const float* dec_masks = (const float*)d_in[3];
    const float* eps       = (const float*)d_in[4];
    const float* W1 = (const float*)d_in[5];
    const float* U1 = (const float*)d_in[6];
    const float* b1 = (const float*)d_in[7];
    const float* W2 = (const float*)d_in[8];
    const float* U2 = (const float*)d_in[9];
    const float* b2 = (const float*)d_in[10];
    const float* W3 = (const float*)d_in[11];
    const float* U3 = (const float*)d_in[12];
    const float* b3 = (const float*)d_in[13];
    const float* W4 = (const float*)d_in[14];
    const float* U4 = (const float*)d_in[15];
    const float* b4 = (const float*)d_in[16];
    const float* W5 = (const float*)d_in[17];
    const float* U5 = (const float*)d_in[18];
    const float* b5 = (const float*)d_in[19];
    const float* W6 = (const float*)d_in[20];
    const float* U6 = (const float*)d_in[21];
    const float* b6 = (const float*)d_in[22];
    const float* Wd = (const float*)d_in[23];
    const float* bd = (const float*)d_in[24];
    float* out = (float*)d_out;

    void *pA, *pB, *pM, *pH34, *pZ, *pUc, *pWc, *pBc;
    cudaGetSymbolAddress(&pA, g_bufA);
    cudaGetSymbolAddress(&pB, g_bufB);
    cudaGetSymbolAddress(&pM, g_mask);
    cudaGetSymbolAddress(&pH34, g_h34);
    cudaGetSymbolAddress(&pZ, g_z);
    cudaGetSymbolAddress(&pUc, g_Uc);
    cudaGetSymbolAddress(&pWc, g_Wc);
    cudaGetSymbolAddress(&pBc, g_bc);
    float* bufA = (float*)pA;
    float* bufB = (float*)pB;
    float* mptr = (float*)pM;
    float* h34  = (float*)pH34;
    float* zbuf = (float*)pZ;
    float* Uc   = (float*)pUc;
    float* Wc   = (float*)pWc;
    float* Bc   = (float*)pBc;

    mask_kernel<<<(BB * TT + 255) / 256, 256>>>(x, mptr);
    combine34_kernel<<<64, 256>>>(W3, U3, b3, W4, U4, b4, Uc, Wc, Bc);

    // encoder GRU1 (H=175, I=4): JT=22, JG=6 -> 192 threads
    launch_gru<175, 4, 192, true, true, true, true>(x, U1, W1, b1, mptr, bufA);

    // encoder GRU2 (H=150, I=175): JT=19, JG=5 -> 160 threads
    launch_gru<150, 175, 160, true, true, true, true>(bufA, U2, W2, b2, mptr, bufB);

    // fused GRU3+GRU4 (H=60, I=150): JT=8, JG=2 -> 64 threads, final state only
    launch_gru<60, 150, 64, false, false, true, false>(bufB, Uc, Wc, Bc, mptr, h34);

    z_kernel<<<(BB * 30 + 255) / 256, 256>>>(h34, eps, zbuf);
    decin_kernel<<<2048, 256>>>(zbuf, tin2, masks, bufA);

    // decoder GRU5 (H=150, I=32): 160 threads
    launch_gru<150, 32, 160, true, true, false, true>(bufA, U5, W5, b5, nullptr, bufB);

    // decoder GRU6 (H=175, I=150): 192 threads
    launch_gru<175, 150, 192, true, true, false, true>(bufB, U6, W6, b6, nullptr, bufA);

    dense_kernel<<<(BB * TT + 7) / 8, 256>>>(bufA, Wd, bd, dec_masks, out);
}

// round 16
// speedup vs baseline: 1.9558x; 1.0166x over previous
#include <cuda_runtime.h>
#include <cstdint>

#define BB 128
#define TT 2048

__device__ float g_bufA[(size_t)BB * TT * 180];
__device__ float g_bufB[(size_t)BB * TT * 180];
__device__ float g_mask[(size_t)BB * TT];
__device__ float g_h34[BB * 60];
__device__ float g_z[BB * 30];
__device__ float g_Uc[60 * 180];
__device__ float g_Wc[150 * 180];
__device__ float g_bc[2 * 180];

__host__ __device__ constexpr int padDim(int v) {
    int h = (v + 3) / 4 * 4;
    if (((h / 4) & 1) == 0) h += 4;
    return h;
}

__device__ __forceinline__ uint32_t smem_u32(const void* p) {
    uint32_t a;
    asm("{ .reg .u64 t; cvta.to.shared.u64 t, %1; cvt.u32.u64 %0, t; }" : "=r"(a) : "l"(p));
    return a;
}
__device__ __forceinline__ uint32_t mapa_shared(uint32_t local, uint32_t rank) {
    uint32_t r;
    asm("mapa.shared::cluster.u32 %0, %1, %2;" : "=r"(r) : "r"(local), "r"(rank));
    return r;
}
__device__ __forceinline__ void st_cluster_f32(uint32_t addr, float v) {
    asm volatile("st.shared::cluster.b32 [%0], %1;" :: "r"(addr), "r"(__float_as_uint(v)));
}
__device__ __forceinline__ void cluster_sync_() {
    asm volatile("barrier.cluster.arrive.aligned;" ::: "memory");
    asm volatile("barrier.cluster.wait.aligned;" ::: "memory");
}
__device__ __forceinline__ void cp_async16(uint32_t dst, const void* src) {
    asm volatile("cp.async.cg.shared.global [%0], [%1], 16;" :: "r"(dst), "l"(src));
}
__device__ __forceinline__ void cp_async4(uint32_t dst, const void* src) {
    asm volatile("cp.async.ca.shared.global [%0], [%1], 4;" :: "r"(dst), "l"(src));
}
__device__ __forceinline__ void cp_commit() {
    asm volatile("cp.async.commit_group;" ::: "memory");
}
__device__ __forceinline__ void cp_wait0() {
    asm volatile("cp.async.wait_group 0;" ::: "memory");
}

__device__ __forceinline__ float hsig(float v) { return fminf(fmaxf(0.2f * v + 0.5f, 0.f), 1.f); }
__device__ __forceinline__ float sigm(float v) { return 1.f / (1.f + expf(-v)); }

// ===================== persistent GRU kernel (register-tiled, 2 CTA/SM) =====================
// Champion (R6) structure, unchanged math, plus a one-shot phase stagger:
// co-resident clusters get (ci & 3) * 1000 cycles of initial offset so their
// FMA phases and cluster barriers interleave instead of colliding.
template <int H, int I, int NTH, bool HSIG, bool TANHA, bool UM, bool WSEQ>
__global__ void __cluster_dims__(8, 1, 1) __launch_bounds__(NTH, 2)
gru_kernel(const float* __restrict__ in_seq, const float* __restrict__ U,
           const float* __restrict__ W, const float* __restrict__ bias,
           const float* __restrict__ mask, float* __restrict__ out_seq)
{
    constexpr int BT = 4, JJT = 4;
    constexpr int HP = padDim(H), IP = padDim(I), KP = HP + IP;
    constexpr int Q = KP / 4, HQ = HP / 4;
    constexpr int JT = (H + 7) / 8;
    constexpr int JG = (JT + JJT - 1) / JJT;
    constexpr int JTp = JG * JJT;
    constexpr int H3 = 3 * H;
    static_assert(NTH == 32 * JG, "threads = 32 per jj-group");

    extern __shared__ float smem[];
    float* sW   = smem;                     // JTp*3*KP (rows zero-padded)
    float* sv   = sW + JTp * 3 * KP;        // 2*BT*KP  (double-buffered [h|x])
    float* sbz  = sv + 2 * BT * KP;         // JTp
    float* sbr  = sbz + JTp;
    float* sbrh = sbr + JTp;
    float* sbxh = sbrh + JTp;
    float* smk  = sbxh + JTp;               // 2*BT
    constexpr int SMTOT = JTp * 3 * KP + 2 * BT * KP + 4 * JTp + 2 * BT;

    const int tid  = threadIdx.x;
    const int rank = blockIdx.x & 7;
    const int ci   = blockIdx.x >> 3;
    const int b0   = ci * BT;
    const int j0   = rank * JT;

    for (int e = tid; e < SMTOT; e += NTH) smem[e] = 0.f;
    __syncthreads();

    // weights: row (jj,g) = [U[:,g*H+j] (k<HP) | W[:,g*H+j] (k>=HP)], zero-padded
    for (int e = tid; e < JT * 3 * KP; e += NTH) {
        int jj = e / (3 * KP);
        int r  = e - jj * (3 * KP);
        int g  = r / KP;
        int k  = r - g * KP;
        int j  = j0 + jj;
        float val = 0.f;
        if (j < H) {
            if (k < HP) { if (k < H) val = U[k * H3 + g * H + j]; }
            else { int i = k - HP; if (i < I) val = W[i * H3 + g * H + j]; }
        }
        sW[(jj * 3 + g) * KP + k] = val;
    }
    if (tid < JT) {
        int j = j0 + tid;
        if (j < H) {
            sbz[tid]  = bias[j] + bias[H3 + j];
            sbr[tid]  = bias[H + j] + bias[H3 + H + j];
            sbxh[tid] = bias[2 * H + j];
            sbrh[tid] = bias[H3 + 2 * H + j];
        }
    }
    __syncthreads();

    const uint32_t svu = smem_u32(sv);
    uint32_t rb[8];
#pragma unroll
    for (int r = 0; r < 8; r++) rb[r] = mapa_shared(svu, (uint32_t)r);

    // stage x(0), mask(0) into phase 0
    constexpr int XOPS = BT * (IP / 4);
    for (int e = tid; e < XOPS; e += NTH) {
        int bb = e / (IP / 4), i4 = e - bb * (IP / 4);
        cp_async16(svu + (uint32_t)((bb * KP + HP + i4 * 4) * 4),
                   in_seq + ((size_t)(b0 + bb) * TT) * IP + i4 * 4);
    }
    if (UM && tid < BT)
        cp_async4(smem_u32(smk + tid), mask + (size_t)(b0 + tid) * TT);
    cp_commit();
    cp_wait0();
    cluster_sync_();

    // ---- one-shot phase stagger: de-phase co-resident clusters.
    // Co-resident CTAs are bid and bid+148 -> clusters ci and ci+18/19; mod-4
    // keys always differ, so every SM pair gets a 1000-3000 cycle offset.
    {
        const unsigned long long delay = (unsigned long long)((ci & 3) * 1000);
        if (delay) {
            unsigned long long s0 = clock64();
            while ((unsigned long long)(clock64() - s0) < delay) { }
        }
    }

    const int w = tid >> 5, lane = tid & 31;

    int p = 0;
    for (int t = 0; t < TT; t++) {
        const int nxt = 1 - p;
        // prefetch x(t+1), mask(t+1)
        if (t + 1 < TT) {
            for (int e = tid; e < XOPS; e += NTH) {
                int bb = e / (IP / 4), i4 = e - bb * (IP / 4);
                cp_async16(svu + (uint32_t)(((nxt * BT + bb) * KP + HP + i4 * 4) * 4),
                           in_seq + ((size_t)(b0 + bb) * TT + (t + 1)) * IP + i4 * 4);
            }
            if (UM && tid < BT)
                cp_async4(smem_u32(smk + nxt * BT + tid),
                          mask + (size_t)(b0 + tid) * TT + (t + 1));
        }
        cp_commit();

        // ---- main accumulation: warp covers 4 b x 4 jj, lanes stride quads
        const float* vc = sv + p * BT * KP;
        float accf[64];
#pragma unroll
        for (int a = 0; a < 64; a++) accf[a] = 0.f;

        for (int g4 = lane; g4 < Q; g4 += 32) {
            const float* vq = vc + g4 * 4;
            float4 vb[BT];
#pragma unroll
            for (int b = 0; b < BT; ++b)
                vb[b] = *reinterpret_cast<const float4*>(vq + b * KP);
            float4 whv[JJT];
#pragma unroll
            for (int jl = 0; jl < JJT; ++jl) {
                const float* wb = sW + ((w * JJT + jl) * 3) * KP + g4 * 4;
                float4 wz = *reinterpret_cast<const float4*>(wb);
                float4 wr = *reinterpret_cast<const float4*>(wb + KP);
                whv[jl]   = *reinterpret_cast<const float4*>(wb + 2 * KP);
#pragma unroll
                for (int b = 0; b < BT; ++b) {
                    const int a = (b * JJT + jl) * 4;
                    accf[a+0] = fmaf(vb[b].x, wz.x, accf[a+0]);
                    accf[a+0] = fmaf(vb[b].y, wz.y, accf[a+0]);
                    accf[a+0] = fmaf(vb[b].z, wz.z, accf[a+0]);
                    accf[a+0] = fmaf(vb[b].w, wz.w, accf[a+0]);
                    accf[a+1] = fmaf(vb[b].x, wr.x, accf[a+1]);
                    accf[a+1] = fmaf(vb[b].y, wr.y, accf[a+1]);
                    accf[a+1] = fmaf(vb[b].z, wr.z, accf[a+1]);
                    accf[a+1] = fmaf(vb[b].w, wr.w, accf[a+1]);
                }
            }
            if (g4 < HQ) {   // h-range: gate-h -> recurrent accumulator (a+2)
#pragma unroll
                for (int jl = 0; jl < JJT; ++jl)
#pragma unroll
                    for (int b = 0; b < BT; ++b) {
                        const int a = (b * JJT + jl) * 4;
                        accf[a+2] = fmaf(vb[b].x, whv[jl].x, accf[a+2]);
                        accf[a+2] = fmaf(vb[b].y, whv[jl].y, accf[a+2]);
                        accf[a+2] = fmaf(vb[b].z, whv[jl].z, accf[a+2]);
                        accf[a+2] = fmaf(vb[b].w, whv[jl].w, accf[a+2]);
                    }
            } else {         // x-range: gate-h -> input accumulator (a+3)
#pragma unroll
                for (int jl = 0; jl < JJT; ++jl)
#pragma unroll
                    for (int b = 0; b < BT; ++b) {
                        const int a = (b * JJT + jl) * 4;
                        accf[a+3] = fmaf(vb[b].x, whv[jl].x, accf[a+3]);
                        accf[a+3] = fmaf(vb[b].y, whv[jl].y, accf[a+3]);
                        accf[a+3] = fmaf(vb[b].z, whv[jl].z, accf[a+3]);
                        accf[a+3] = fmaf(vb[b].w, whv[jl].w, accf[a+3]);
                    }
            }
        }

        // ---- splitting butterfly: 4 rounds over lane bits 0..3
#pragma unroll
        for (int s = 0; s < 4; ++s) {
            const int n = 64 >> (s + 1);
            const bool hi = (lane >> s) & 1;
#pragma unroll
            for (int i = 0; i < n; ++i) {
                float send = hi ? accf[i] : accf[i + n];
                float recv = __shfl_xor_sync(0xffffffffu, send, 1 << s);
                accf[i] = (hi ? accf[i + n] : accf[i]) + recv;
            }
        }
        // finish across lane bit 4, keeping all 4 gate accs (dup in l, l^16)
#pragma unroll
        for (int i = 0; i < 4; ++i)
            accf[i] += __shfl_xor_sync(0xffffffffu, accf[i], 16);

        // ---- in-register epilogue on owner lanes
        if (lane < 16) {
            const int item = ((lane & 1) << 3) | ((lane & 2) << 1) |
                             ((lane & 4) >> 1) | ((lane & 8) >> 3);
            const int b = item >> 2, jl = item & 3;
            const int jj = w * JJT + jl;
            const int j  = j0 + jj;
            if (jj < JT && j < H) {
                float az  = accf[0] + sbz[jj];
                float ar  = accf[1] + sbr[jj];
                float arh = accf[2] + sbrh[jj];
                float axh = accf[3] + sbxh[jj];
                float z = HSIG ? hsig(az) : sigm(az);
                float r = HSIG ? hsig(ar) : sigm(ar);
                float hh = axh + r * arh;
                if (TANHA) hh = tanhf(hh);
                float hprev = vc[b * KP + j];
                float hn = z * hprev + (1.f - z) * hh;
                if (UM) { if (smk[p * BT + b] == 0.f) hn = hprev; }

                const uint32_t off = (uint32_t)(((nxt * BT + b) * KP + j) * 4);
#pragma unroll
                for (int r8 = 0; r8 < 8; r8++) st_cluster_f32(rb[r8] + off, hn);

                if (WSEQ) out_seq[((size_t)(b0 + b) * TT + t) * HP + j] = hn;
            }
        }
        cp_wait0();
        cluster_sync_();
        p = nxt;
    }

    if (!WSEQ) {
        if (tid < JT * BT) {
            const int b = tid & 3, jj = tid >> 2;
            const int j = j0 + jj;
            if (j < H) out_seq[(size_t)(b0 + b) * H + j] = sv[(p * BT + b) * KP + j];
        }
    }
}

// ===================== small kernels =====================
__global__ void mask_kernel(const float* __restrict__ x, float* __restrict__ m) {
    int idx = blockIdx.x * blockDim.x + threadIdx.x;
    if (idx < BB * TT) {
        float4 v = ((const float4*)x)[idx];
        m[idx] = (v.x != 0.f || v.y != 0.f || v.z != 0.f || v.w != 0.f) ? 1.f : 0.f;
    }
}

__global__ void combine34_kernel(const float* __restrict__ W3, const float* __restrict__ U3,
                                 const float* __restrict__ b3, const float* __restrict__ W4,
                                 const float* __restrict__ U4, const float* __restrict__ b4,
                                 float* __restrict__ Uc, float* __restrict__ Wc,
                                 float* __restrict__ bc) {
    const int NU = 60 * 180, NW = 150 * 180, NBc = 2 * 180;
    for (int e = blockIdx.x * blockDim.x + threadIdx.x; e < NU + NW + NBc;
         e += gridDim.x * blockDim.x) {
        if (e < NU) {
            int k = e / 180, col = e % 180;
            int g = col / 60, jj = col % 60;
            float v = 0.f;
            if (jj < 30) { if (k < 30)  v = U3[k * 90 + g * 30 + jj]; }
            else         { if (k >= 30) v = U4[(k - 30) * 90 + g * 30 + (jj - 30)]; }
            Uc[e] = v;
        } else if (e < NU + NW) {
            int e2 = e - NU;
            int i = e2 / 180, col = e2 % 180;
            int g = col / 60, jj = col % 60;
            Wc[e2] = (jj < 30) ? W3[i * 90 + g * 30 + jj] : W4[i * 90 + g * 30 + (jj - 30)];
        } else {
            int e2 = e - NU - NW;
            int rr = e2 / 180, col = e2 % 180;
            int g = col / 60, jj = col % 60;
            bc[e2] = (jj < 30) ? b3[rr * 90 + g * 30 + jj] : b4[rr * 90 + g * 30 + (jj - 30)];
        }
    }
}

__global__ void z_kernel(const float* __restrict__ h34, const float* __restrict__ eps,
                         float* __restrict__ z) {
    int idx = blockIdx.x * blockDim.x + threadIdx.x;
    if (idx < BB * 30) {
        int b = idx / 30, c = idx % 30;
        z[idx] = h34[b * 60 + c] + expf(0.5f * h34[b * 60 + 30 + c]) * eps[idx];
    }
}

__global__ void decin_kernel(const float* __restrict__ z, const float* __restrict__ tin2,
                             const float* __restrict__ masks, float* __restrict__ dec_in) {
    const size_t N = (size_t)BB * TT * 36;
    for (size_t idx = (size_t)blockIdx.x * blockDim.x + threadIdx.x; idx < N;
         idx += (size_t)gridDim.x * blockDim.x) {
        size_t b = idx / ((size_t)TT * 36);
        size_t rem = idx % ((size_t)TT * 36);
        size_t t = rem / 36;
        int c = (int)(rem % 36);
        float v = 0.f;
        if (c < 30)      v = z[b * 30 + c] * masks[(b * TT + t) * 32 + c];
        else if (c < 32) v = tin2[(b * TT + t) * 2 + (c - 30)] * masks[(b * TT + t) * 32 + c];
        dec_in[idx] = v;
    }
}

__global__ void dense_kernel(const float* __restrict__ h6, const float* __restrict__ Wd,
                             const float* __restrict__ bd, const float* __restrict__ dec_masks,
                             float* __restrict__ out) {
    int gtid = blockIdx.x * blockDim.x + threadIdx.x;
    int row = gtid >> 5;
    int lane = gtid & 31;
    if (row >= BB * TT) return;
    float s = 0.f;
    const float* hrow = h6 + (size_t)row * 180;
    for (int k = lane; k < 175; k += 32) s = fmaf(hrow[k], Wd[k], s);
#pragma unroll
    for (int off = 16; off; off >>= 1) s += __shfl_down_sync(0xffffffffu, s, off);
    if (lane == 0) out[row] = tanhf(s + bd[0]) * dec_masks[row];
}

// ===================== host-side launch helper =====================
template <int H, int I, int NTH, bool HSIG, bool TANHA, bool UM, bool WSEQ>
static void launch_gru(const float* in_seq, const float* U, const float* W, const float* bias,
                       const float* mask, float* out_seq) {
    constexpr int BT = 4, JJT = 4;
    constexpr int HP = padDim(H), IP = padDim(I), KP = HP + IP;
    constexpr int JT = (H + 7) / 8;
    constexpr int JG = (JT + JJT - 1) / JJT;
    constexpr int JTp = JG * JJT;
    constexpr int SMTOT = JTp * 3 * KP + 2 * BT * KP + 4 * JTp + 2 * BT;
    constexpr int smem_bytes = SMTOT * 4;
    auto fn = gru_kernel<H, I, NTH, HSIG, TANHA, UM, WSEQ>;
    cudaFuncSetAttribute(fn, cudaFuncAttributeMaxDynamicSharedMemorySize, smem_bytes);
    cudaFuncSetAttribute(fn, cudaFuncAttributeNonPortableClusterSizeAllowed, 1);
    fn<<<256, NTH, smem_bytes>>>(in_seq, U, W, bias, mask, out_seq);
}

extern "C" void kernel_launch(void* const* d_in, const int* in_sizes, int n_in,
                              void* d_out, int out_size) {
    const float* x         = (const float*)d_in[0];
    const float* tin2      = (const float*)d_in[1];
    const float* masks     = (const float*)d_in[2];
    const float* dec_masks = (const float*)d_in[3];
    const float* eps       = (const float*)d_in[4];
    const float* W1 = (const float*)d_in[5];
    const float* U1 = (const float*)d_in[6];
    const float* b1 = (const float*)d_in[7];
    const float* W2 = (const float*)d_in[8];
    const float* U2 = (const float*)d_in[9];
    const float* b2 = (const float*)d_in[10];
    const float* W3 = (const float*)d_in[11];
    const float* U3 = (const float*)d_in[12];
    const float* b3 = (const float*)d_in[13];
    const float* W4 = (const float*)d_in[14];
    const float* U4 = (const float*)d_in[15];
    const float* b4 = (const float*)d_in[16];
    const float* W5 = (const float*)d_in[17];
    const float* U5 = (const float*)d_in[18];
    const float* b5 = (const float*)d_in[19];
    const float* W6 = (const float*)d_in[20];
    const float* U6 = (const float*)d_in[21];
    const float* b6 = (const float*)d_in[22];
    const float* Wd = (const float*)d_in[23];
    const float* bd = (const float*)d_in[24];
    float* out = (float*)d_out;

    void *pA, *pB, *pM, *pH34, *pZ, *pUc, *pWc, *pBc;
    cudaGetSymbolAddress(&pA, g_bufA);
    cudaGetSymbolAddress(&pB, g_bufB);
    cudaGetSymbolAddress(&pM, g_mask);
    cudaGetSymbolAddress(&pH34, g_h34);
    cudaGetSymbolAddress(&pZ, g_z);
    cudaGetSymbolAddress(&pUc, g_Uc);
    cudaGetSymbolAddress(&pWc, g_Wc);
    cudaGetSymbolAddress(&pBc, g_bc);
    float* bufA = (float*)pA;
    float* bufB = (float*)pB;
    float* mptr = (float*)pM;
    float* h34  = (float*)pH34;
    float* zbuf = (float*)pZ;
    float* Uc   = (float*)pUc;
    float* Wc   = (float*)pWc;
    float* Bc   = (float*)pBc;

    mask_kernel<<<(BB * TT + 255) / 256, 256>>>(x, mptr);
    combine34_kernel<<<64, 256>>>(W3, U3, b3, W4, U4, b4, Uc, Wc, Bc);

    // encoder GRU1 (H=175, I=4): JT=22, JG=6 -> 192 threads
    launch_gru<175, 4, 192, true, true, true, true>(x, U1, W1, b1, mptr, bufA);

    // encoder GRU2 (H=150, I=175): JT=19, JG=5 -> 160 threads
    launch_gru<150, 175, 160, true, true, true, true>(bufA, U2, W2, b2, mptr, bufB);

    // fused GRU3+GRU4 (H=60, I=150): JT=8, JG=2 -> 64 threads, final state only
    launch_gru<60, 150, 64, false, false, true, false>(bufB, Uc, Wc, Bc, mptr, h34);

    z_kernel<<<(BB * 30 + 255) / 256, 256>>>(h34, eps, zbuf);
    decin_kernel<<<2048, 256>>>(zbuf, tin2, masks, bufA);

    // decoder GRU5 (H=150, I=32): 160 threads
    launch_gru<150, 32, 160, true, true, false, true>(bufA, U5, W5, b5, nullptr, bufB);

    // decoder GRU6 (H=175, I=150): 192 threads
    launch_gru<175, 150, 192, true, true, false, true>(bufB, U6, W6, b6, nullptr, bufA);

    dense_kernel<<<(BB * TT + 7) / 8, 256>>>(bufA, Wd, bd, dec_masks, out);
}